// round 13
// baseline (speedup 1.0000x reference)
#include <cuda_runtime.h>
#include <math.h>

// NarrowParabolicEq — time-parallel: banded operator squaring + 20 chains.
// T = S^10 (one save interval, radius-6 band; validated numerics from the
// single-chain kernel). Build T^2,T^4,...,T^128 by numeric banded squaring
// (radii 6,9,12,16,22,30,44,64). Chain k starts at y_{10k} = product of
// binary-power operators applied to y0 (powers of one matrix -> commute),
// then runs only ~10 sequential T-applications. 20 chains on 20 SMs.
// Sequential span: 200 -> ~17 banded ops. Multi-kernel launches = global syncs.

#define NPTS 500
#define NLVL 8
#define TAPW 129              // tap offsets -64..64, center index 64
#define NCH  20
#define NTH  256
#define YSLOTS 528

typedef unsigned long long u64;
union F2U { float2 f; u64 u; };

__device__ __forceinline__ u64 pk2(float lo, float hi) { F2U x; x.f.x = lo; x.f.y = hi; return x.u; }
__device__ __forceinline__ float lo2(u64 v) { F2U a; a.u = v; return a.f.x; }
__device__ __forceinline__ float hi2(u64 v) { F2U a; a.u = v; return a.f.y; }

__device__ __forceinline__ u64 fma2(u64 a, u64 b, u64 c)
{ u64 d; asm("fma.rn.f32x2 %0,%1,%2,%3;" : "=l"(d) : "l"(a), "l"(b), "l"(c)); return d; }
__device__ __forceinline__ u64 add2(u64 a, u64 b)
{ u64 d; asm("add.rn.f32x2 %0,%1,%2;" : "=l"(d) : "l"(a), "l"(b)); return d; }
__device__ __forceinline__ u64 mul2(u64 a, u64 b)
{ u64 d; asm("mul.rn.f32x2 %0,%1,%2;" : "=l"(d) : "l"(a), "l"(b)); return d; }

// ---- scratch (static device globals; no runtime allocation) ----
__device__ float gP[NLVL * NPTS * TAPW];
__device__ float gQ[NLVL * NPTS * TAPW];
__device__ float2 gY0[NPTS];
__device__ float2 gStart[NCH * NPTS];

__device__ __constant__ int dRLV[NLVL] = {6, 9, 12, 16, 22, 30, 44, 64};

__device__ __forceinline__ void coeffs_at(int q, double K0d, double refc, double refd,
                                          float* hcli, float* hch2)
{
    if (q >= 1 && q <= NPTS - 2) {
        double dx = 2000.0 / 499.0;
        double cli = (1.0 / (dx * dx)) / (2.0 * K0d);
        double z  = 2000.0 * (double)q / 499.0;
        double zz = 2.0 * (z - refd) / refd;
        double c  = refc * (1.0 + 0.00737 * (zz - 1.0 + exp(-zz)));
        double het = (1500.0 / c) * (1500.0 / c) - 1.0;
        double ch = K0d * het;
        *hcli = (float)(0.1 * cli);
        *hch2 = (float)(0.1 * (ch - 2.0 * cli));
    } else {
        *hcli = 0.0f; *hch2 = 0.0f;
    }
}

// ---------------- Kernel A: base taps (T = S^10, radius 6) + y0 ----------------
__global__ void k_build0(const float* __restrict__ params)
{
    const int p = threadIdx.x;
    if (p >= NPTS) return;

    const double PI  = 3.14159265358979323846;
    const double K0d = 2.0 * PI * 50.0 / 1500.0;
    const double refc = (double)params[0];
    const double refd = (double)params[1];

    // y0
    {
        double ww  = sqrt(2.0 * log(2.0)) / (K0d * sin(PI / 180.0 * 1.5));
        double amp = 1.0 / (sqrt(PI) * ww);
        double z = 2000.0 * (double)p / 499.0;
        double a = (z - 100.0) / ww;
        gY0[p] = make_float2((float)(amp * exp(-a * a)), 0.f);
    }

    // degree-14 coefficients of R(z)^10 (double convolution), parity-folded
    float pcF[15], qcF[15];
    {
        double cD[7] = {1.0, 1.0, 0.5, 1.0/6.0, 1.0/24.0, 1.0/120.0, 1.0/600.0};
        double R2[15], R4[15], R8[15], R10[15];
        for (int m = 0; m < 15; m++) {
            double s = 0.0;
            for (int j = 0; j <= 6; j++)
                if (m - j >= 0 && m - j <= 6) s += cD[j] * cD[m - j];
            R2[m] = s;
        }
        for (int m = 0; m < 15; m++) {
            double s = 0.0;
            for (int j = 0; j <= m; j++) s += R2[j] * R2[m - j];
            R4[m] = s;
        }
        for (int m = 0; m < 15; m++) {
            double s = 0.0;
            for (int j = 0; j <= m; j++) s += R4[j] * R4[m - j];
            R8[m] = s;
        }
        for (int m = 0; m < 15; m++) {
            double s = 0.0;
            for (int j = 0; j <= m; j++) s += R8[j] * R2[m - j];
            R10[m] = s;
        }
        for (int m = 0; m < 15; m++) {
            if ((m & 1) == 0) {
                pcF[m] = (float)(((m & 3) == 0) ? R10[m] : -R10[m]);
                qcF[m] = 0.f;
            } else {
                qcF[m] = (float)(((m & 3) == 1) ? R10[m] : -R10[m]);
                pcF[m] = 0.f;
            }
        }
    }

    // band row via 19-wide x 14-deep zeta-power register recurrence
    float cliA[19], ch2A[19];
    #pragma unroll
    for (int j = 0; j < 19; j++)
        coeffs_at(p - 9 + j, K0d, refc, refd, &cliA[j], &ch2A[j]);

    float w[19], Pt[13], Qt[13];
    #pragma unroll
    for (int j = 0; j < 19; j++) w[j] = 0.f;
    w[9] = 1.f;
    #pragma unroll
    for (int j = 0; j < 13; j++) { Pt[j] = 0.f; Qt[j] = 0.f; }
    Pt[6] = pcF[0];

    #pragma unroll
    for (int k = 1; k <= 14; k++) {
        float nw[19];
        #pragma unroll
        for (int o = 0; o < 19; o++) {
            float acc = w[o] * ch2A[o];
            if (o > 0)  acc += w[o - 1] * cliA[o - 1];
            if (o < 18) acc += w[o + 1] * cliA[o + 1];
            nw[o] = acc;
        }
        #pragma unroll
        for (int o = 0; o < 19; o++) w[o] = nw[o];
        #pragma unroll
        for (int o2 = 0; o2 < 13; o2++) {
            Pt[o2] += pcF[k] * w[o2 + 3];
            Qt[o2] += qcF[k] * w[o2 + 3];
        }
    }

    #pragma unroll
    for (int j = 0; j < 13; j++) {
        gP[p * TAPW + 58 + j] = Pt[j];
        gQ[p * TAPW + 58 + j] = Qt[j];
    }
}

// ---------------- Kernel B: banded squaring T_{L+1} = T_L * T_L ----------------
__global__ void k_square(int L, int Rin, int Rout)
{
    const int p = blockIdx.x;
    const int d = (int)threadIdx.x - 64;
    if (d < -Rout || d > Rout) return;

    const float* Pi = gP + (size_t)L * NPTS * TAPW;
    const float* Qi = gQ + (size_t)L * NPTS * TAPW;

    float pp = 0.f, qq = 0.f;
    int olo = (d - Rin > -Rin) ? d - Rin : -Rin;
    int ohi = (d + Rin <  Rin) ? d + Rin :  Rin;
    if (olo < -p) olo = -p;
    if (ohi > NPTS - 1 - p) ohi = NPTS - 1 - p;

    const float* rowp = Pi + p * TAPW + 64;
    const float* rowq = Qi + p * TAPW + 64;
    for (int o = olo; o <= ohi; o++) {
        float a = rowp[o], b = rowq[o];
        int idx2 = (p + o) * TAPW + 64 + (d - o);
        float c = Pi[idx2], e = Qi[idx2];
        pp += a * c - b * e;
        qq += a * e + b * c;
    }
    gP[(size_t)(L + 1) * NPTS * TAPW + p * TAPW + 64 + d] = pp;
    gQ[(size_t)(L + 1) * NPTS * TAPW + p * TAPW + 64 + d] = qq;
}

// ---------------- Kernel C: chain starting vectors ----------------
__global__ __launch_bounds__(NTH, 1) void k_starts(int m, int nitv)
{
    __shared__ float2 ya[NPTS], yb[NPTS];
    const int k = blockIdx.x, t = threadIdx.x;
    const int n0 = m * k;
    if (n0 > nitv) return;

    for (int p = t; p < NPTS; p += NTH) ya[p] = gY0[p];
    __syncthreads();

    float2* src = ya;
    float2* dst = yb;
    for (int L = 0; L < NLVL; L++) {
        if (!((n0 >> L) & 1)) continue;
        const int R = dRLV[L];
        const float* Pi = gP + (size_t)L * NPTS * TAPW;
        const float* Qi = gQ + (size_t)L * NPTS * TAPW;
        for (int p = t; p < NPTS; p += NTH) {
            float re = 0.f, im = 0.f;
            int olo = (-R > -p) ? -R : -p;
            int ohi = (R < NPTS - 1 - p) ? R : NPTS - 1 - p;
            const float* rp = Pi + p * TAPW + 64;
            const float* rq = Qi + p * TAPW + 64;
            for (int o = olo; o <= ohi; o++) {
                float a = rp[o], b = rq[o];
                float2 v = src[p + o];
                re += a * v.x - b * v.y;
                im += a * v.y + b * v.x;
            }
            dst[p] = make_float2(re, im);
        }
        __syncthreads();
        float2* tmp = src; src = dst; dst = tmp;
    }
    for (int p = t; p < NPTS; p += NTH) gStart[k * NPTS + p] = src[p];
}

// ---------------- Kernel D: 20 parallel chains of ~10 applications ----------------
__global__ __launch_bounds__(NTH, 1) void k_chains(float* __restrict__ out,
                                                   int n_save, int m)
{
    __shared__ __align__(16) u64 YA[YSLOTS];
    __shared__ __align__(16) u64 YB[YSLOTS];

    const int k = blockIdx.x, t = threadIdx.x;
    const int p0 = 2 * t;
    const int half = n_save * NPTS;
    const int nitv = n_save - 1;
    const int n0 = m * k;
    if (n0 > nitv) return;

    // taps from level 0 (radius 6), packed; rows >= NPTS get zeros
    u64 Pa[13], Qa[13], Pb[13], Qb[13];
    #pragma unroll
    for (int j = 0; j < 13; j++) {
        float pa = 0.f, qa = 0.f, pb = 0.f, qb = 0.f;
        if (p0 < NPTS)     { pa = gP[p0 * TAPW + 58 + j];       qa = gQ[p0 * TAPW + 58 + j]; }
        if (p0 + 1 < NPTS) { pb = gP[(p0 + 1) * TAPW + 58 + j]; qb = gQ[(p0 + 1) * TAPW + 58 + j]; }
        Pa[j] = pk2(pa, pa); Qa[j] = pk2(qa, qa);
        Pb[j] = pk2(pb, pb); Qb[j] = pk2(qb, qb);
    }

    for (int j = t; j < YSLOTS; j += NTH) { YA[j] = 0ull; YB[j] = 0ull; }
    __syncthreads();

    u64 y0p = 0ull, y1p = 0ull;
    if (p0 < NPTS) {
        F2U a; a.f = gStart[k * NPTS + p0];     y0p = a.u;
        if (p0 + 1 < NPTS) { a.f = gStart[k * NPTS + p0 + 1]; y1p = a.u; }
    }
    YA[p0 + 6] = y0p;
    YA[p0 + 7] = y1p;
    __syncthreads();

    // write start row n0
    if (p0 < NPTS) {
        int row = n0 * NPTS + p0;
        out[row]        = lo2(y0p);
        out[half + row] = hi2(y0p);
        if (p0 + 1 < NPTS) {
            out[row + 1]        = lo2(y1p);
            out[half + row + 1] = hi2(y1p);
        }
    }

    const float4* RA = ((const float4*)YA) + t;
    const float4* RB = ((const float4*)YB) + t;
    float4* WA = ((float4*)YA) + (t + 3);
    float4* WB = ((float4*)YB) + (t + 3);

#define STEP(RSRC, WDST)                                                     \
    {                                                                        \
        u64 v[14];                                                           \
        _Pragma("unroll")                                                    \
        for (int j = 0; j < 7; j++) {                                        \
            float4 f = (RSRC)[j];                                            \
            v[2*j] = pk2(f.x, f.y); v[2*j + 1] = pk2(f.z, f.w);              \
        }                                                                    \
        u64 pa0 = mul2(Pa[0], v[0]);   u64 pa1 = mul2(Pa[1], v[1]);          \
        pa0 = fma2(Pa[2],  v[2],  pa0); pa1 = fma2(Pa[3],  v[3],  pa1);      \
        pa0 = fma2(Pa[4],  v[4],  pa0); pa1 = fma2(Pa[5],  v[5],  pa1);      \
        pa0 = fma2(Pa[6],  v[6],  pa0); pa1 = fma2(Pa[7],  v[7],  pa1);      \
        pa0 = fma2(Pa[8],  v[8],  pa0); pa1 = fma2(Pa[9],  v[9],  pa1);      \
        pa0 = fma2(Pa[10], v[10], pa0); pa1 = fma2(Pa[11], v[11], pa1);      \
        pa0 = fma2(Pa[12], v[12], pa0);                                      \
        u64 qa0 = mul2(Qa[0], v[0]);   u64 qa1 = mul2(Qa[1], v[1]);          \
        qa0 = fma2(Qa[2],  v[2],  qa0); qa1 = fma2(Qa[3],  v[3],  qa1);      \
        qa0 = fma2(Qa[4],  v[4],  qa0); qa1 = fma2(Qa[5],  v[5],  qa1);      \
        qa0 = fma2(Qa[6],  v[6],  qa0); qa1 = fma2(Qa[7],  v[7],  qa1);      \
        qa0 = fma2(Qa[8],  v[8],  qa0); qa1 = fma2(Qa[9],  v[9],  qa1);      \
        qa0 = fma2(Qa[10], v[10], qa0); qa1 = fma2(Qa[11], v[11], qa1);      \
        qa0 = fma2(Qa[12], v[12], qa0);                                      \
        u64 pb0 = mul2(Pb[0], v[1]);   u64 pb1 = mul2(Pb[1], v[2]);          \
        pb0 = fma2(Pb[2],  v[3],  pb0); pb1 = fma2(Pb[3],  v[4],  pb1);      \
        pb0 = fma2(Pb[4],  v[5],  pb0); pb1 = fma2(Pb[5],  v[6],  pb1);      \
        pb0 = fma2(Pb[6],  v[7],  pb0); pb1 = fma2(Pb[7],  v[8],  pb1);      \
        pb0 = fma2(Pb[8],  v[9],  pb0); pb1 = fma2(Pb[9],  v[10], pb1);      \
        pb0 = fma2(Pb[10], v[11], pb0); pb1 = fma2(Pb[11], v[12], pb1);      \
        pb0 = fma2(Pb[12], v[13], pb0);                                      \
        u64 qb0 = mul2(Qb[0], v[1]);   u64 qb1 = mul2(Qb[1], v[2]);          \
        qb0 = fma2(Qb[2],  v[3],  qb0); qb1 = fma2(Qb[3],  v[4],  qb1);      \
        qb0 = fma2(Qb[4],  v[5],  qb0); qb1 = fma2(Qb[5],  v[6],  qb1);      \
        qb0 = fma2(Qb[6],  v[7],  qb0); qb1 = fma2(Qb[7],  v[8],  qb1);      \
        qb0 = fma2(Qb[8],  v[9],  qb0); qb1 = fma2(Qb[9],  v[10], qb1);      \
        qb0 = fma2(Qb[10], v[11], qb0); qb1 = fma2(Qb[11], v[12], qb1);      \
        qb0 = fma2(Qb[12], v[13], qb0);                                      \
        u64 uP0 = add2(pa0, pa1);  u64 uQ0 = add2(qa0, qa1);                 \
        u64 uP1 = add2(pb0, pb1);  u64 uQ1 = add2(qb0, qb1);                 \
        F2U U0, V0, U1, V1; U0.u = uP0; V0.u = uQ0; U1.u = uP1; V1.u = uQ1;  \
        y0p = pk2(U0.f.x - V0.f.y, U0.f.y + V0.f.x);                         \
        y1p = pk2(U1.f.x - V1.f.y, U1.f.y + V1.f.x);                         \
        float4 sv; sv.x = lo2(y0p); sv.y = hi2(y0p);                         \
        sv.z = lo2(y1p); sv.w = hi2(y1p);                                    \
        *(WDST) = sv;                                                        \
        __syncthreads();                                                     \
    }

    // rows n0+1..top, where next chain (if any) provides row n0+m as its start
    int lastrow = (n0 + m < nitv) ? n0 + m : nitv;
    bool next_exists = (k + 1 < NCH) && (m * (k + 1) <= nitv);
    int top = next_exists ? (m * (k + 1) - 1) : lastrow;
    int napps = top - n0;

    int fl = 0;
    for (int a = 0; a < napps; a++) {
        if (!fl) { STEP(RA, WB) } else { STEP(RB, WA) }
        if (p0 < NPTS) {
            int row = (n0 + 1 + a) * NPTS + p0;
            out[row]        = lo2(y0p);
            out[half + row] = hi2(y0p);
            if (p0 + 1 < NPTS) {
                out[row + 1]        = lo2(y1p);
                out[half + row + 1] = hi2(y1p);
            }
        }
        fl ^= 1;
    }
#undef STEP
}

extern "C" void kernel_launch(void* const* d_in, const int* in_sizes, int n_in,
                              void* d_out, int out_size)
{
    int p_idx = 1, t_idx = 0;
    if (n_in >= 2 && in_sizes[0] == 2 && in_sizes[1] != 2) { p_idx = 0; t_idx = 1; }
    const float* params = (const float*)d_in[p_idx];
    const int n_save = in_sizes[t_idx];
    const int nitv = n_save - 1;
    const int m = (nitv + NCH - 1) / NCH;          // intervals per chain (10)

    static const int RLV_h[NLVL] = {6, 9, 12, 16, 22, 30, 44, 64};

    k_build0<<<1, 512>>>(params);
    for (int L = 0; L < NLVL - 1; L++)
        k_square<<<NPTS, TAPW>>>(L, RLV_h[L], RLV_h[L + 1]);
    k_starts<<<NCH, NTH>>>(m, nitv);
    k_chains<<<NCH, NTH>>>((float*)d_out, n_save, m);
}

// round 14
// speedup vs baseline: 1.7370x; 1.7370x over previous
#include <cuda_runtime.h>
#include <math.h>

// NarrowParabolicEq — time-parallel, SINGLE persistent kernel.
// Phases (125 co-resident blocks, spin global barriers):
//  P0: build T = S^10 band taps (radius 6) + y0        [R13-validated math]
//  P1-P7: banded squaring T^2..T^128, smem-tiled        [radii 6,9,12,16,22,30,44,64]
//  P8: 25 chain starts y_{8k} via binary powers (coalesced, transposed operator)
//  P9: 25 chains x ~8 T-applications (R12/13-validated inner loop)
// Operator storage TRANSPOSED: gOp[level][tap][point] (float2 = (P,Q)).

#define NPTS 500
#define NTH  256
#define NBLK 125
#define NLVL 8
#define TAPW 129
#define NCH  25
#define MITV 8
#define YSLOTS 528
#define SMEM_BYTES (68 * 1024)

typedef unsigned long long u64;
union F2U { float2 f; u64 u; };

__device__ __forceinline__ u64 pk2(float lo, float hi) { F2U x; x.f.x = lo; x.f.y = hi; return x.u; }
__device__ __forceinline__ float lo2(u64 v) { F2U a; a.u = v; return a.f.x; }
__device__ __forceinline__ float hi2(u64 v) { F2U a; a.u = v; return a.f.y; }

__device__ __forceinline__ u64 fma2(u64 a, u64 b, u64 c)
{ u64 d; asm("fma.rn.f32x2 %0,%1,%2,%3;" : "=l"(d) : "l"(a), "l"(b), "l"(c)); return d; }
__device__ __forceinline__ u64 add2(u64 a, u64 b)
{ u64 d; asm("add.rn.f32x2 %0,%1,%2;" : "=l"(d) : "l"(a), "l"(b)); return d; }
__device__ __forceinline__ u64 mul2(u64 a, u64 b)
{ u64 d; asm("mul.rn.f32x2 %0,%1,%2;" : "=l"(d) : "l"(a), "l"(b)); return d; }

// ---- device globals (static, no runtime allocation) ----
__device__ float2 gOp[NLVL][TAPW][NPTS];   // (P,Q) taps, TRANSPOSED (tap-major)
__device__ float2 gY0[NPTS];
__device__ float2 gStart[NCH][NPTS];
__device__ int gCnt;
__device__ int gGen;   // monotonic across launches; never reset

__constant__ int cRLV[NLVL] = {6, 9, 12, 16, 22, 30, 44, 64};

// Global spin barrier. Monotonic generation: safe across graph replays because
// gGen cannot advance past a barrier until every block of THIS launch arrives.
__device__ __forceinline__ void gsync(int& myg)
{
    __syncthreads();
    if (threadIdx.x == 0) {
        __threadfence();
        if (atomicAdd(&gCnt, 1) == NBLK - 1) {
            atomicExch(&gCnt, 0);
            __threadfence();
            atomicAdd(&gGen, 1);
        } else {
            while (atomicAdd(&gGen, 0) == myg) __nanosleep(64);
        }
        myg++;
        __threadfence();
    }
    __syncthreads();
}

__device__ __forceinline__ void coeffs_at(int q, double K0d, double refc, double refd,
                                          float* hcli, float* hch2)
{
    if (q >= 1 && q <= NPTS - 2) {
        double dx = 2000.0 / 499.0;
        double cli = (1.0 / (dx * dx)) / (2.0 * K0d);
        double z  = 2000.0 * (double)q / 499.0;
        double zz = 2.0 * (z - refd) / refd;
        double c  = refc * (1.0 + 0.00737 * (zz - 1.0 + exp(-zz)));
        double het = (1500.0 / c) * (1500.0 / c) - 1.0;
        double ch = K0d * het;
        *hcli = (float)(0.1 * cli);
        *hch2 = (float)(0.1 * (ch - 2.0 * cli));
    } else {
        *hcli = 0.0f; *hch2 = 0.0f;
    }
}

extern __shared__ float2 sbuf[];

__global__ __launch_bounds__(NTH, 1)
void pe_all(const float* __restrict__ params, float* __restrict__ out, int n_save)
{
    const int tid = threadIdx.x;
    const int b   = blockIdx.x;
    int myg = 0;
    if (tid == 0) myg = atomicAdd(&gGen, 0);

    const double PI  = 3.14159265358979323846;
    const double K0d = 2.0 * PI * 50.0 / 1500.0;
    const double refc = (double)params[0];
    const double refd = (double)params[1];

    // ================= P0: base taps (T = S^10, radius 6) + y0 =================
    if (tid < 4) {
        int p = 4 * b + tid;
        if (p < NPTS) {
            // y0
            {
                double ww  = sqrt(2.0 * log(2.0)) / (K0d * sin(PI / 180.0 * 1.5));
                double amp = 1.0 / (sqrt(PI) * ww);
                double z = 2000.0 * (double)p / 499.0;
                double a = (z - 100.0) / ww;
                gY0[p] = make_float2((float)(amp * exp(-a * a)), 0.f);
            }
            // degree-14 coefficients of R(z)^10 (double convolution), parity-folded
            float pcF[15], qcF[15];
            {
                double cD[7] = {1.0, 1.0, 0.5, 1.0/6.0, 1.0/24.0, 1.0/120.0, 1.0/600.0};
                double R2[15], R4[15], R8[15], R10[15];
                for (int m = 0; m < 15; m++) {
                    double s = 0.0;
                    for (int j = 0; j <= 6; j++)
                        if (m - j >= 0 && m - j <= 6) s += cD[j] * cD[m - j];
                    R2[m] = s;
                }
                for (int m = 0; m < 15; m++) {
                    double s = 0.0;
                    for (int j = 0; j <= m; j++) s += R2[j] * R2[m - j];
                    R4[m] = s;
                }
                for (int m = 0; m < 15; m++) {
                    double s = 0.0;
                    for (int j = 0; j <= m; j++) s += R4[j] * R4[m - j];
                    R8[m] = s;
                }
                for (int m = 0; m < 15; m++) {
                    double s = 0.0;
                    for (int j = 0; j <= m; j++) s += R8[j] * R2[m - j];
                    R10[m] = s;
                }
                for (int m = 0; m < 15; m++) {
                    if ((m & 1) == 0) {
                        pcF[m] = (float)(((m & 3) == 0) ? R10[m] : -R10[m]);
                        qcF[m] = 0.f;
                    } else {
                        qcF[m] = (float)(((m & 3) == 1) ? R10[m] : -R10[m]);
                        pcF[m] = 0.f;
                    }
                }
            }
            // band row via 19-wide x 14-deep zeta-power register recurrence
            float cliA[19], ch2A[19];
            #pragma unroll
            for (int j = 0; j < 19; j++)
                coeffs_at(p - 9 + j, K0d, refc, refd, &cliA[j], &ch2A[j]);
            float w[19], Pt[13], Qt[13];
            #pragma unroll
            for (int j = 0; j < 19; j++) w[j] = 0.f;
            w[9] = 1.f;
            #pragma unroll
            for (int j = 0; j < 13; j++) { Pt[j] = 0.f; Qt[j] = 0.f; }
            Pt[6] = pcF[0];
            #pragma unroll
            for (int k = 1; k <= 14; k++) {
                float nw[19];
                #pragma unroll
                for (int o = 0; o < 19; o++) {
                    float acc = w[o] * ch2A[o];
                    if (o > 0)  acc += w[o - 1] * cliA[o - 1];
                    if (o < 18) acc += w[o + 1] * cliA[o + 1];
                    nw[o] = acc;
                }
                #pragma unroll
                for (int o = 0; o < 19; o++) w[o] = nw[o];
                #pragma unroll
                for (int o2 = 0; o2 < 13; o2++) {
                    Pt[o2] += pcF[k] * w[o2 + 3];
                    Qt[o2] += qcF[k] * w[o2 + 3];
                }
            }
            #pragma unroll
            for (int j = 0; j < 13; j++)
                gOp[0][58 + j][p] = make_float2(Pt[j], Qt[j]);
        }
    }
    gsync(myg);

    // ================= P1..P7: smem-tiled banded squaring =================
    for (int L = 0; L < NLVL - 1; L++) {
        const int Rin  = cRLV[L];
        const int Rout = cRLV[L + 1];
        const int Win   = 2 * Rin + 1;
        const int rowsIn = 4 + 2 * Rin;
        const int rowsP  = rowsIn + 1;          // bank pad
        const int r0 = 4 * b;

        // stage input window: s[tap][lr], lr = local row (coalesced over rows)
        for (int i = tid; i < Win * rowsIn; i += NTH) {
            int tap = i / rowsIn;
            int lr  = i - tap * rowsIn;
            int r   = r0 - Rin + lr;
            sbuf[tap * rowsP + lr] =
                (r >= 0 && r < NPTS) ? gOp[L][64 - Rin + tap][r] : make_float2(0.f, 0.f);
        }
        __syncthreads();

        const int Wout = 2 * Rout + 1;
        for (int i = tid; i < 4 * Wout; i += NTH) {
            int row = i / Wout;
            int d   = i - row * Wout - Rout;
            int r   = r0 + row;
            if (r >= NPTS) continue;
            int olo = (-Rin > d - Rin) ? -Rin : d - Rin;
            int ohi = ( Rin < d + Rin) ?  Rin : d + Rin;
            float pp = 0.f, qq = 0.f;
            for (int o = olo; o <= ohi; o++) {
                float2 A = sbuf[(o + Rin) * rowsP + (Rin + row)];
                float2 B = sbuf[(d - o + Rin) * rowsP + (Rin + row + o)];
                pp += A.x * B.x - A.y * B.y;
                qq += A.x * B.y + A.y * B.x;
            }
            gOp[L + 1][64 + d][r] = make_float2(pp, qq);
        }
        gsync(myg);
    }

    // ================= P8: chain starting vectors =================
    if (b < NCH) {
        const int nitv = n_save - 1;
        const int n0 = MITV * b;
        if (n0 <= nitv) {
            float2* va = sbuf;
            float2* vb = sbuf + 512;
            for (int p = tid; p < NPTS; p += NTH) va[p] = gY0[p];
            __syncthreads();
            float2* src = va;
            float2* dst = vb;
            for (int L = 0; L < NLVL; L++) {
                if (!((n0 >> L) & 1)) continue;
                const int R = cRLV[L];
                for (int p = tid; p < NPTS; p += NTH) {
                    int olo = (p < R) ? -p : -R;
                    int ohi = (NPTS - 1 - p < R) ? NPTS - 1 - p : R;
                    float a1x = 0.f, a1y = 0.f, a2x = 0.f, a2y = 0.f;
                    for (int o = olo; o <= ohi; o++) {
                        float2 PQ = gOp[L][64 + o][p];   // coalesced over p
                        float2 v  = src[p + o];
                        a1x += PQ.x * v.x;  a1y += PQ.x * v.y;
                        a2x += PQ.y * v.x;  a2y += PQ.y * v.y;
                    }
                    dst[p] = make_float2(a1x - a2y, a1y + a2x);
                }
                __syncthreads();
                float2* tmp = src; src = dst; dst = tmp;
            }
            for (int p = tid; p < NPTS; p += NTH) gStart[b][p] = src[p];
        }
    }
    gsync(myg);

    // ================= P9: 25 chains x ~8 T-applications =================
    if (b < NCH) {
        const int nitv = n_save - 1;
        const int n0 = MITV * b;
        if (n0 <= nitv) {
            u64* YA = (u64*)sbuf;
            u64* YB = YA + YSLOTS;
            const int p0 = 2 * tid;
            const int half = n_save * NPTS;

            u64 Pa[13], Qa[13], Pb[13], Qb[13];
            #pragma unroll
            for (int j = 0; j < 13; j++) {
                float2 t0 = (p0 < NPTS) ? gOp[0][58 + j][p0] : make_float2(0.f, 0.f);
                float2 t1 = (p0 + 1 < NPTS) ? gOp[0][58 + j][p0 + 1] : make_float2(0.f, 0.f);
                Pa[j] = pk2(t0.x, t0.x);  Qa[j] = pk2(t0.y, t0.y);
                Pb[j] = pk2(t1.x, t1.x);  Qb[j] = pk2(t1.y, t1.y);
            }

            for (int j = tid; j < YSLOTS; j += NTH) { YA[j] = 0ull; YB[j] = 0ull; }
            __syncthreads();

            u64 y0p = 0ull, y1p = 0ull;
            if (p0 < NPTS) {
                F2U a; a.f = gStart[b][p0]; y0p = a.u;
                if (p0 + 1 < NPTS) { a.f = gStart[b][p0 + 1]; y1p = a.u; }
            }
            YA[p0 + 6] = y0p;
            YA[p0 + 7] = y1p;
            __syncthreads();

            if (p0 < NPTS) {
                int row = n0 * NPTS + p0;
                out[row]        = lo2(y0p);
                out[half + row] = hi2(y0p);
                if (p0 + 1 < NPTS) {
                    out[row + 1]        = lo2(y1p);
                    out[half + row + 1] = hi2(y1p);
                }
            }

            const float4* RA = ((const float4*)YA) + tid;
            const float4* RB = ((const float4*)YB) + tid;
            float4* WA = ((float4*)YA) + (tid + 3);
            float4* WB = ((float4*)YB) + (tid + 3);

#define STEP(RSRC, WDST)                                                     \
    {                                                                        \
        u64 v[14];                                                           \
        _Pragma("unroll")                                                    \
        for (int j = 0; j < 7; j++) {                                        \
            float4 f = (RSRC)[j];                                            \
            v[2*j] = pk2(f.x, f.y); v[2*j + 1] = pk2(f.z, f.w);              \
        }                                                                    \
        u64 pa0 = mul2(Pa[0], v[0]);   u64 pa1 = mul2(Pa[1], v[1]);          \
        pa0 = fma2(Pa[2],  v[2],  pa0); pa1 = fma2(Pa[3],  v[3],  pa1);      \
        pa0 = fma2(Pa[4],  v[4],  pa0); pa1 = fma2(Pa[5],  v[5],  pa1);      \
        pa0 = fma2(Pa[6],  v[6],  pa0); pa1 = fma2(Pa[7],  v[7],  pa1);      \
        pa0 = fma2(Pa[8],  v[8],  pa0); pa1 = fma2(Pa[9],  v[9],  pa1);      \
        pa0 = fma2(Pa[10], v[10], pa0); pa1 = fma2(Pa[11], v[11], pa1);      \
        pa0 = fma2(Pa[12], v[12], pa0);                                      \
        u64 qa0 = mul2(Qa[0], v[0]);   u64 qa1 = mul2(Qa[1], v[1]);          \
        qa0 = fma2(Qa[2],  v[2],  qa0); qa1 = fma2(Qa[3],  v[3],  qa1);      \
        qa0 = fma2(Qa[4],  v[4],  qa0); qa1 = fma2(Qa[5],  v[5],  qa1);      \
        qa0 = fma2(Qa[6],  v[6],  qa0); qa1 = fma2(Qa[7],  v[7],  qa1);      \
        qa0 = fma2(Qa[8],  v[8],  qa0); qa1 = fma2(Qa[9],  v[9],  qa1);      \
        qa0 = fma2(Qa[10], v[10], qa0); qa1 = fma2(Qa[11], v[11], qa1);      \
        qa0 = fma2(Qa[12], v[12], qa0);                                      \
        u64 pb0 = mul2(Pb[0], v[1]);   u64 pb1 = mul2(Pb[1], v[2]);          \
        pb0 = fma2(Pb[2],  v[3],  pb0); pb1 = fma2(Pb[3],  v[4],  pb1);      \
        pb0 = fma2(Pb[4],  v[5],  pb0); pb1 = fma2(Pb[5],  v[6],  pb1);      \
        pb0 = fma2(Pb[6],  v[7],  pb0); pb1 = fma2(Pb[7],  v[8],  pb1);      \
        pb0 = fma2(Pb[8],  v[9],  pb0); pb1 = fma2(Pb[9],  v[10], pb1);      \
        pb0 = fma2(Pb[10], v[11], pb0); pb1 = fma2(Pb[11], v[12], pb1);      \
        pb0 = fma2(Pb[12], v[13], pb0);                                      \
        u64 qb0 = mul2(Qb[0], v[1]);   u64 qb1 = mul2(Qb[1], v[2]);          \
        qb0 = fma2(Qb[2],  v[3],  qb0); qb1 = fma2(Qb[3],  v[4],  qb1);      \
        qb0 = fma2(Qb[4],  v[5],  qb0); qb1 = fma2(Qb[5],  v[6],  qb1);      \
        qb0 = fma2(Qb[6],  v[7],  qb0); qb1 = fma2(Qb[7],  v[8],  qb1);      \
        qb0 = fma2(Qb[8],  v[9],  qb0); qb1 = fma2(Qb[9],  v[10], qb1);      \
        qb0 = fma2(Qb[10], v[11], qb0); qb1 = fma2(Qb[11], v[12], qb1);      \
        qb0 = fma2(Qb[12], v[13], qb0);                                      \
        u64 uP0 = add2(pa0, pa1);  u64 uQ0 = add2(qa0, qa1);                 \
        u64 uP1 = add2(pb0, pb1);  u64 uQ1 = add2(qb0, qb1);                 \
        F2U U0, V0, U1, V1; U0.u = uP0; V0.u = uQ0; U1.u = uP1; V1.u = uQ1;  \
        y0p = pk2(U0.f.x - V0.f.y, U0.f.y + V0.f.x);                         \
        y1p = pk2(U1.f.x - V1.f.y, U1.f.y + V1.f.x);                         \
        float4 sv; sv.x = lo2(y0p); sv.y = hi2(y0p);                         \
        sv.z = lo2(y1p); sv.w = hi2(y1p);                                    \
        *(WDST) = sv;                                                        \
        __syncthreads();                                                     \
    }

            int lastrow = (n0 + MITV < nitv) ? n0 + MITV : nitv;
            bool next_exists = (b + 1 < NCH) && (MITV * (b + 1) <= nitv);
            int top = next_exists ? (MITV * (b + 1) - 1) : lastrow;
            int napps = top - n0;

            int fl = 0;
            for (int a = 0; a < napps; a++) {
                if (!fl) { STEP(RA, WB) } else { STEP(RB, WA) }
                if (p0 < NPTS) {
                    int row = (n0 + 1 + a) * NPTS + p0;
                    out[row]        = lo2(y0p);
                    out[half + row] = hi2(y0p);
                    if (p0 + 1 < NPTS) {
                        out[row + 1]        = lo2(y1p);
                        out[half + row + 1] = hi2(y1p);
                    }
                }
                fl ^= 1;
            }
#undef STEP
        }
    }
}

extern "C" void kernel_launch(void* const* d_in, const int* in_sizes, int n_in,
                              void* d_out, int out_size)
{
    int p_idx = 1, t_idx = 0;
    if (n_in >= 2 && in_sizes[0] == 2 && in_sizes[1] != 2) { p_idx = 0; t_idx = 1; }
    const float* params = (const float*)d_in[p_idx];
    const int n_save = in_sizes[t_idx];

    cudaFuncSetAttribute(pe_all, cudaFuncAttributeMaxDynamicSharedMemorySize, SMEM_BYTES);
    pe_all<<<NBLK, NTH, SMEM_BYTES>>>(params, (float*)d_out, n_save);
}

// round 15
// speedup vs baseline: 1.8793x; 1.0819x over previous
#include <cuda_runtime.h>
#include <math.h>

// NarrowParabolicEq — time-parallel persistent kernel, ALL-FP32 init.
//  P0: T = S^10 band taps (radius 6) + y0, pure fp32 (expf)     [1 barrier]
//  Ladder L=0..6: banded squaring T^{2^{L+1}}, smem-tiled;       [7 barriers]
//     chain blocks apply freshly-built levels to their smem start
//     vector in the slack after each barrier (powers commute).
//  P9: 25 chains x ~8 T-applications, fully block-local.         [0 barriers]
// Operator storage TRANSPOSED: gOp[level][tap][point] (float2 = (P,Q)).

#define NPTS 500
#define NTH  256
#define NBLK 125
#define NLVL 8
#define TAPW 129
#define NCH  25
#define MITV 8
#define YSLOTS 528
#define SMEM_BYTES (76 * 1024)
#define VOFF0 8448            // float2 index of chain vector buffer 0
#define VOFF1 8960            // float2 index of chain vector buffer 1

typedef unsigned long long u64;
union F2U { float2 f; u64 u; };

__device__ __forceinline__ u64 pk2(float lo, float hi) { F2U x; x.f.x = lo; x.f.y = hi; return x.u; }
__device__ __forceinline__ float lo2(u64 v) { F2U a; a.u = v; return a.f.x; }
__device__ __forceinline__ float hi2(u64 v) { F2U a; a.u = v; return a.f.y; }

__device__ __forceinline__ u64 fma2(u64 a, u64 b, u64 c)
{ u64 d; asm("fma.rn.f32x2 %0,%1,%2,%3;" : "=l"(d) : "l"(a), "l"(b), "l"(c)); return d; }
__device__ __forceinline__ u64 add2(u64 a, u64 b)
{ u64 d; asm("add.rn.f32x2 %0,%1,%2;" : "=l"(d) : "l"(a), "l"(b)); return d; }
__device__ __forceinline__ u64 mul2(u64 a, u64 b)
{ u64 d; asm("mul.rn.f32x2 %0,%1,%2;" : "=l"(d) : "l"(a), "l"(b)); return d; }

__device__ float2 gOp[NLVL][TAPW][NPTS];
__device__ int gCnt;
__device__ int gGen;   // monotonic; never reset (graph-replay safe)

__constant__ int cRLV[NLVL] = {6, 9, 12, 16, 22, 30, 44, 64};

__device__ __forceinline__ void gsync(int& myg)
{
    __syncthreads();
    if (threadIdx.x == 0) {
        __threadfence();
        if (atomicAdd(&gCnt, 1) == NBLK - 1) {
            atomicExch(&gCnt, 0);
            __threadfence();
            atomicAdd(&gGen, 1);
        } else {
            while (atomicAdd(&gGen, 0) == myg) __nanosleep(32);
        }
        myg++;
        __threadfence();
    }
    __syncthreads();
}

// fp32 operator coefficients at point q
__device__ __forceinline__ void coeffs_at(int q, float refc, float refd,
                                          float* hcli, float* hch2)
{
    const float K0 = 0.209439510239f;          // 2*pi*50/1500
    if (q >= 1 && q <= NPTS - 2) {
        const float dx = 2000.0f / 499.0f;
        float cli = (1.0f / (dx * dx)) / (2.0f * K0);
        float z  = (2000.0f / 499.0f) * (float)q;
        float zz = 2.0f * (z - refd) / refd;
        float c  = refc * (1.0f + 0.00737f * (zz - 1.0f + expf(-zz)));
        float r  = 1500.0f / c;
        float het = r * r - 1.0f;
        float ch = K0 * het;
        *hcli = 0.1f * cli;
        *hch2 = 0.1f * (ch - 2.0f * cli);
    } else {
        *hcli = 0.0f; *hch2 = 0.0f;
    }
}

extern __shared__ float2 sbuf[];

__global__ __launch_bounds__(NTH, 1)
void pe_all(const float* __restrict__ params, float* __restrict__ out, int n_save)
{
    const int tid = threadIdx.x;
    const int b   = blockIdx.x;
    int myg = 0;
    if (tid == 0) myg = atomicAdd(&gGen, 0);

    const float refc = params[0];
    const float refd = params[1];
    const int nitv = n_save - 1;
    const int n0 = MITV * b;           // chain start interval (blocks b < NCH)
    const bool is_chain = (b < NCH) && (n0 <= nitv);

    float2* v0 = sbuf + VOFF0;
    float2* v1 = sbuf + VOFF1;

    // ================= P0: base taps (fp32) + chain y0 =================
    if (tid < 4) {
        int p = 4 * b + tid;
        if (p < NPTS) {
            // R(z)^10 coefficients, fp32 convolutions (values are modest: <=~1200)
            float pcF[15], qcF[15];
            {
                float cD[7] = {1.f, 1.f, 0.5f, 1.f/6.f, 1.f/24.f, 1.f/120.f, 1.f/600.f};
                float R2[15], R4[15], R8[15], R10[15];
                for (int m = 0; m < 15; m++) {
                    float s = 0.f;
                    for (int j = 0; j <= 6; j++)
                        if (m - j >= 0 && m - j <= 6) s += cD[j] * cD[m - j];
                    R2[m] = s;
                }
                for (int m = 0; m < 15; m++) {
                    float s = 0.f;
                    for (int j = 0; j <= m; j++) s += R2[j] * R2[m - j];
                    R4[m] = s;
                }
                for (int m = 0; m < 15; m++) {
                    float s = 0.f;
                    for (int j = 0; j <= m; j++) s += R4[j] * R4[m - j];
                    R8[m] = s;
                }
                for (int m = 0; m < 15; m++) {
                    float s = 0.f;
                    for (int j = 0; j <= m; j++) s += R8[j] * R2[m - j];
                    R10[m] = s;
                }
                for (int m = 0; m < 15; m++) {
                    if ((m & 1) == 0) {
                        pcF[m] = ((m & 3) == 0) ? R10[m] : -R10[m];
                        qcF[m] = 0.f;
                    } else {
                        qcF[m] = ((m & 3) == 1) ? R10[m] : -R10[m];
                        pcF[m] = 0.f;
                    }
                }
            }
            // band row via 19-wide x 14-deep zeta-power register recurrence
            float cliA[19], ch2A[19];
            #pragma unroll
            for (int j = 0; j < 19; j++)
                coeffs_at(p - 9 + j, refc, refd, &cliA[j], &ch2A[j]);
            float w[19], Pt[13], Qt[13];
            #pragma unroll
            for (int j = 0; j < 19; j++) w[j] = 0.f;
            w[9] = 1.f;
            #pragma unroll
            for (int j = 0; j < 13; j++) { Pt[j] = 0.f; Qt[j] = 0.f; }
            Pt[6] = pcF[0];
            #pragma unroll
            for (int k = 1; k <= 14; k++) {
                float nw[19];
                #pragma unroll
                for (int o = 0; o < 19; o++) {
                    float acc = w[o] * ch2A[o];
                    if (o > 0)  acc += w[o - 1] * cliA[o - 1];
                    if (o < 18) acc += w[o + 1] * cliA[o + 1];
                    nw[o] = acc;
                }
                #pragma unroll
                for (int o = 0; o < 19; o++) w[o] = nw[o];
                #pragma unroll
                for (int o2 = 0; o2 < 13; o2++) {
                    Pt[o2] += pcF[k] * w[o2 + 3];
                    Qt[o2] += qcF[k] * w[o2 + 3];
                }
            }
            #pragma unroll
            for (int j = 0; j < 13; j++)
                gOp[0][58 + j][p] = make_float2(Pt[j], Qt[j]);
        }
    }
    // chain blocks: y0 into local smem vector (fp32 aperture, elev=0 -> real)
    if (is_chain) {
        const float K0 = 0.209439510239f;
        const float SINE = 0.0261769483f;                  // sin(1.5 deg)
        float ww  = sqrtf(2.0f * logf(2.0f)) / (K0 * SINE);
        float amp = 1.0f / (sqrtf(3.14159265358979f) * ww);
        for (int p = tid; p < NPTS; p += NTH) {
            float z = (2000.0f / 499.0f) * (float)p;
            float a = (z - 100.0f) / ww;
            v0[p] = make_float2(amp * expf(-a * a), 0.f);
        }
    }
    gsync(myg);

    // ============ Ladder + overlapped chain-start products ============
    float2* src = v0;
    float2* dst = v1;
    for (int L = 0; L < NLVL - 1; L++) {
        const int Rin  = cRLV[L];
        const int Rout = cRLV[L + 1];
        const int Win   = 2 * Rin + 1;
        const int rowsIn = 4 + 2 * Rin;
        const int rowsP  = rowsIn + 1;
        const int r0 = 4 * b;

        for (int i = tid; i < Win * rowsIn; i += NTH) {
            int tap = i / rowsIn;
            int lr  = i - tap * rowsIn;
            int r   = r0 - Rin + lr;
            sbuf[tap * rowsP + lr] =
                (r >= 0 && r < NPTS) ? gOp[L][64 - Rin + tap][r] : make_float2(0.f, 0.f);
        }
        __syncthreads();

        const int Wout = 2 * Rout + 1;
        for (int i = tid; i < 4 * Wout; i += NTH) {
            int row = i / Wout;
            int d   = i - row * Wout - Rout;
            int r   = r0 + row;
            if (r >= NPTS) continue;
            int olo = (-Rin > d - Rin) ? -Rin : d - Rin;
            int ohi = ( Rin < d + Rin) ?  Rin : d + Rin;
            float pp = 0.f, qq = 0.f;
            for (int o = olo; o <= ohi; o++) {
                float2 A = sbuf[(o + Rin) * rowsP + (Rin + row)];
                float2 B = sbuf[(d - o + Rin) * rowsP + (Rin + row + o)];
                pp += A.x * B.x - A.y * B.y;
                qq += A.x * B.y + A.y * B.x;
            }
            gOp[L + 1][64 + d][r] = make_float2(pp, qq);
        }
        gsync(myg);   // level L+1 globally visible

        // chain blocks: multiply running vector by T^{2^{L+1}} if that bit set
        if (is_chain && ((n0 >> (L + 1)) & 1)) {
            const int R = cRLV[L + 1];
            for (int p = tid; p < NPTS; p += NTH) {
                int olo = (p < R) ? -p : -R;
                int ohi = (NPTS - 1 - p < R) ? NPTS - 1 - p : R;
                float a1x = 0.f, a1y = 0.f, a2x = 0.f, a2y = 0.f;
                for (int o = olo; o <= ohi; o++) {
                    float2 PQ = gOp[L + 1][64 + o][p];
                    float2 v  = src[p + o];
                    a1x += PQ.x * v.x;  a1y += PQ.x * v.y;
                    a2x += PQ.y * v.x;  a2y += PQ.y * v.y;
                }
                dst[p] = make_float2(a1x - a2y, a1y + a2x);
            }
            __syncthreads();
            float2* tmp = src; src = dst; dst = tmp;
        }
    }

    // ================= P9: chains, fully local =================
    if (is_chain) {
        u64* YA = (u64*)sbuf;
        u64* YB = YA + YSLOTS;
        const int p0 = 2 * tid;
        const int half = n_save * NPTS;

        u64 Pa[13], Qa[13], Pb[13], Qb[13];
        #pragma unroll
        for (int j = 0; j < 13; j++) {
            float2 t0 = (p0 < NPTS) ? gOp[0][58 + j][p0] : make_float2(0.f, 0.f);
            float2 t1 = (p0 + 1 < NPTS) ? gOp[0][58 + j][p0 + 1] : make_float2(0.f, 0.f);
            Pa[j] = pk2(t0.x, t0.x);  Qa[j] = pk2(t0.y, t0.y);
            Pb[j] = pk2(t1.x, t1.x);  Qb[j] = pk2(t1.y, t1.y);
        }

        for (int j = tid; j < YSLOTS; j += NTH) { YA[j] = 0ull; YB[j] = 0ull; }
        __syncthreads();

        u64 y0p = 0ull, y1p = 0ull;
        if (p0 < NPTS) {
            F2U a; a.f = src[p0]; y0p = a.u;
            if (p0 + 1 < NPTS) { a.f = src[p0 + 1]; y1p = a.u; }
        }
        YA[p0 + 6] = y0p;
        YA[p0 + 7] = y1p;
        __syncthreads();

        if (p0 < NPTS) {
            int row = n0 * NPTS + p0;
            out[row]        = lo2(y0p);
            out[half + row] = hi2(y0p);
            if (p0 + 1 < NPTS) {
                out[row + 1]        = lo2(y1p);
                out[half + row + 1] = hi2(y1p);
            }
        }

        const float4* RA = ((const float4*)YA) + tid;
        const float4* RB = ((const float4*)YB) + tid;
        float4* WA = ((float4*)YA) + (tid + 3);
        float4* WB = ((float4*)YB) + (tid + 3);

#define STEP(RSRC, WDST)                                                     \
    {                                                                        \
        u64 v[14];                                                           \
        _Pragma("unroll")                                                    \
        for (int j = 0; j < 7; j++) {                                        \
            float4 f = (RSRC)[j];                                            \
            v[2*j] = pk2(f.x, f.y); v[2*j + 1] = pk2(f.z, f.w);              \
        }                                                                    \
        u64 pa0 = mul2(Pa[0], v[0]);   u64 pa1 = mul2(Pa[1], v[1]);          \
        pa0 = fma2(Pa[2],  v[2],  pa0); pa1 = fma2(Pa[3],  v[3],  pa1);      \
        pa0 = fma2(Pa[4],  v[4],  pa0); pa1 = fma2(Pa[5],  v[5],  pa1);      \
        pa0 = fma2(Pa[6],  v[6],  pa0); pa1 = fma2(Pa[7],  v[7],  pa1);      \
        pa0 = fma2(Pa[8],  v[8],  pa0); pa1 = fma2(Pa[9],  v[9],  pa1);      \
        pa0 = fma2(Pa[10], v[10], pa0); pa1 = fma2(Pa[11], v[11], pa1);      \
        pa0 = fma2(Pa[12], v[12], pa0);                                      \
        u64 qa0 = mul2(Qa[0], v[0]);   u64 qa1 = mul2(Qa[1], v[1]);          \
        qa0 = fma2(Qa[2],  v[2],  qa0); qa1 = fma2(Qa[3],  v[3],  qa1);      \
        qa0 = fma2(Qa[4],  v[4],  qa0); qa1 = fma2(Qa[5],  v[5],  qa1);      \
        qa0 = fma2(Qa[6],  v[6],  qa0); qa1 = fma2(Qa[7],  v[7],  qa1);      \
        qa0 = fma2(Qa[8],  v[8],  qa0); qa1 = fma2(Qa[9],  v[9],  qa1);      \
        qa0 = fma2(Qa[10], v[10], qa0); qa1 = fma2(Qa[11], v[11], qa1);      \
        qa0 = fma2(Qa[12], v[12], qa0);                                      \
        u64 pb0 = mul2(Pb[0], v[1]);   u64 pb1 = mul2(Pb[1], v[2]);          \
        pb0 = fma2(Pb[2],  v[3],  pb0); pb1 = fma2(Pb[3],  v[4],  pb1);      \
        pb0 = fma2(Pb[4],  v[5],  pb0); pb1 = fma2(Pb[5],  v[6],  pb1);      \
        pb0 = fma2(Pb[6],  v[7],  pb0); pb1 = fma2(Pb[7],  v[8],  pb1);      \
        pb0 = fma2(Pb[8],  v[9],  pb0); pb1 = fma2(Pb[9],  v[10], pb1);      \
        pb0 = fma2(Pb[10], v[11], pb0); pb1 = fma2(Pb[11], v[12], pb1);      \
        pb0 = fma2(Pb[12], v[13], pb0);                                      \
        u64 qb0 = mul2(Qb[0], v[1]);   u64 qb1 = mul2(Qb[1], v[2]);          \
        qb0 = fma2(Qb[2],  v[3],  qb0); qb1 = fma2(Qb[3],  v[4],  qb1);      \
        qb0 = fma2(Qb[4],  v[5],  qb0); qb1 = fma2(Qb[5],  v[6],  qb1);      \
        qb0 = fma2(Qb[6],  v[7],  qb0); qb1 = fma2(Qb[7],  v[8],  qb1);      \
        qb0 = fma2(Qb[8],  v[9],  qb0); qb1 = fma2(Qb[9],  v[10], qb1);      \
        qb0 = fma2(Qb[10], v[11], qb0); qb1 = fma2(Qb[11], v[12], qb1);      \
        qb0 = fma2(Qb[12], v[13], qb0);                                      \
        u64 uP0 = add2(pa0, pa1);  u64 uQ0 = add2(qa0, qa1);                 \
        u64 uP1 = add2(pb0, pb1);  u64 uQ1 = add2(qb0, qb1);                 \
        F2U U0, V0, U1, V1; U0.u = uP0; V0.u = uQ0; U1.u = uP1; V1.u = uQ1;  \
        y0p = pk2(U0.f.x - V0.f.y, U0.f.y + V0.f.x);                         \
        y1p = pk2(U1.f.x - V1.f.y, U1.f.y + V1.f.x);                         \
        float4 sv; sv.x = lo2(y0p); sv.y = hi2(y0p);                         \
        sv.z = lo2(y1p); sv.w = hi2(y1p);                                    \
        *(WDST) = sv;                                                        \
        __syncthreads();                                                     \
    }

        int lastrow = (n0 + MITV < nitv) ? n0 + MITV : nitv;
        bool next_exists = (b + 1 < NCH) && (MITV * (b + 1) <= nitv);
        int top = next_exists ? (MITV * (b + 1) - 1) : lastrow;
        int napps = top - n0;

        int fl = 0;
        for (int a = 0; a < napps; a++) {
            if (!fl) { STEP(RA, WB) } else { STEP(RB, WA) }
            if (p0 < NPTS) {
                int row = (n0 + 1 + a) * NPTS + p0;
                out[row]        = lo2(y0p);
                out[half + row] = hi2(y0p);
                if (p0 + 1 < NPTS) {
                    out[row + 1]        = lo2(y1p);
                    out[half + row + 1] = hi2(y1p);
                }
            }
            fl ^= 1;
        }
#undef STEP
    }
}

extern "C" void kernel_launch(void* const* d_in, const int* in_sizes, int n_in,
                              void* d_out, int out_size)
{
    int p_idx = 1, t_idx = 0;
    if (n_in >= 2 && in_sizes[0] == 2 && in_sizes[1] != 2) { p_idx = 0; t_idx = 1; }
    const float* params = (const float*)d_in[p_idx];
    const int n_save = in_sizes[t_idx];

    cudaFuncSetAttribute(pe_all, cudaFuncAttributeMaxDynamicSharedMemorySize, SMEM_BYTES);
    pe_all<<<NBLK, NTH, SMEM_BYTES>>>(params, (float*)d_out, n_save);
}

// round 16
// speedup vs baseline: 1.8900x; 1.0057x over previous
#include <cuda_runtime.h>
#include <math.h>

// NarrowParabolicEq — time-parallel persistent kernel, fp32 init,
// NON-RMW global barrier (release store + volatile-load polling).
//  P0: T = S^10 band taps (radius 6) + y0                        [1 barrier]
//  Ladder L=0..6: banded squaring T^{2^{L+1}}, smem-tiled;        [7 barriers]
//     chain blocks fold their start-product matvecs into the slack.
//  P9: 25 chains x ~8 T-applications, fully block-local.          [0 barriers]

#define NPTS 500
#define NTH  256
#define NBLK 125
#define NLVL 8
#define TAPW 129
#define NCH  25
#define MITV 8
#define YSLOTS 528
#define SMEM_BYTES (76 * 1024)
#define VOFF0 8448
#define VOFF1 8960

typedef unsigned long long u64;
union F2U { float2 f; u64 u; };

__device__ __forceinline__ u64 pk2(float lo, float hi) { F2U x; x.f.x = lo; x.f.y = hi; return x.u; }
__device__ __forceinline__ float lo2(u64 v) { F2U a; a.u = v; return a.f.x; }
__device__ __forceinline__ float hi2(u64 v) { F2U a; a.u = v; return a.f.y; }

__device__ __forceinline__ u64 fma2(u64 a, u64 b, u64 c)
{ u64 d; asm("fma.rn.f32x2 %0,%1,%2,%3;" : "=l"(d) : "l"(a), "l"(b), "l"(c)); return d; }
__device__ __forceinline__ u64 add2(u64 a, u64 b)
{ u64 d; asm("add.rn.f32x2 %0,%1,%2;" : "=l"(d) : "l"(a), "l"(b)); return d; }
__device__ __forceinline__ u64 mul2(u64 a, u64 b)
{ u64 d; asm("mul.rn.f32x2 %0,%1,%2;" : "=l"(d) : "l"(a), "l"(b)); return d; }

__device__ float2 gOp[NLVL][TAPW][NPTS];
__device__ int gCnt;
__device__ volatile int gGen;    // monotonic; release-store by last arriver only

__constant__ int cRLV[NLVL] = {6, 9, 12, 16, 22, 30, 44, 64};

// Non-RMW barrier: arrivals via one atomicAdd per block; release via plain
// volatile store; polling via plain volatile loads (no atomic serialization).
__device__ __forceinline__ void gsync(int& myg)
{
    __syncthreads();
    if (threadIdx.x == 0) {
        __threadfence();                       // publish this block's writes
        if (atomicAdd(&gCnt, 1) == NBLK - 1) {
            gCnt = 0;                          // safe: all blocks are inside
            __threadfence();
            gGen = myg + 1;                    // release
        } else {
            while (gGen == myg) { }            // plain L2 loads, non-serializing
        }
        myg++;
        __threadfence();                       // acquire
    }
    __syncthreads();
}

__device__ __forceinline__ void coeffs_at(int q, float refc, float refd,
                                          float* hcli, float* hch2)
{
    const float K0 = 0.209439510239f;
    if (q >= 1 && q <= NPTS - 2) {
        const float dx = 2000.0f / 499.0f;
        float cli = (1.0f / (dx * dx)) / (2.0f * K0);
        float z  = (2000.0f / 499.0f) * (float)q;
        float zz = 2.0f * (z - refd) / refd;
        float c  = refc * (1.0f + 0.00737f * (zz - 1.0f + expf(-zz)));
        float r  = 1500.0f / c;
        float het = r * r - 1.0f;
        float ch = K0 * het;
        *hcli = 0.1f * cli;
        *hch2 = 0.1f * (ch - 2.0f * cli);
    } else {
        *hcli = 0.0f; *hch2 = 0.0f;
    }
}

extern __shared__ float2 sbuf[];

__global__ __launch_bounds__(NTH, 1)
void pe_all(const float* __restrict__ params, float* __restrict__ out, int n_save)
{
    const int tid = threadIdx.x;
    const int b   = blockIdx.x;
    int myg = 0;
    if (tid == 0) myg = gGen;      // monotonic; stream ordering => no race

    const float refc = params[0];
    const float refd = params[1];
    const int nitv = n_save - 1;
    const int n0 = MITV * b;
    const bool is_chain = (b < NCH) && (n0 <= nitv);

    float2* v0 = sbuf + VOFF0;
    float2* v1 = sbuf + VOFF1;

    // ================= P0: base taps (fp32) + chain y0 =================
    if (tid < 4) {
        int p = 4 * b + tid;
        if (p < NPTS) {
            float pcF[15], qcF[15];
            {
                float cD[7] = {1.f, 1.f, 0.5f, 1.f/6.f, 1.f/24.f, 1.f/120.f, 1.f/600.f};
                float R2[15], R4[15], R8[15], R10[15];
                for (int m = 0; m < 15; m++) {
                    float s = 0.f;
                    for (int j = 0; j <= 6; j++)
                        if (m - j >= 0 && m - j <= 6) s += cD[j] * cD[m - j];
                    R2[m] = s;
                }
                for (int m = 0; m < 15; m++) {
                    float s = 0.f;
                    for (int j = 0; j <= m; j++) s += R2[j] * R2[m - j];
                    R4[m] = s;
                }
                for (int m = 0; m < 15; m++) {
                    float s = 0.f;
                    for (int j = 0; j <= m; j++) s += R4[j] * R4[m - j];
                    R8[m] = s;
                }
                for (int m = 0; m < 15; m++) {
                    float s = 0.f;
                    for (int j = 0; j <= m; j++) s += R8[j] * R2[m - j];
                    R10[m] = s;
                }
                for (int m = 0; m < 15; m++) {
                    if ((m & 1) == 0) {
                        pcF[m] = ((m & 3) == 0) ? R10[m] : -R10[m];
                        qcF[m] = 0.f;
                    } else {
                        qcF[m] = ((m & 3) == 1) ? R10[m] : -R10[m];
                        pcF[m] = 0.f;
                    }
                }
            }
            float cliA[19], ch2A[19];
            #pragma unroll
            for (int j = 0; j < 19; j++)
                coeffs_at(p - 9 + j, refc, refd, &cliA[j], &ch2A[j]);
            float w[19], Pt[13], Qt[13];
            #pragma unroll
            for (int j = 0; j < 19; j++) w[j] = 0.f;
            w[9] = 1.f;
            #pragma unroll
            for (int j = 0; j < 13; j++) { Pt[j] = 0.f; Qt[j] = 0.f; }
            Pt[6] = pcF[0];
            #pragma unroll
            for (int k = 1; k <= 14; k++) {
                float nw[19];
                #pragma unroll
                for (int o = 0; o < 19; o++) {
                    float acc = w[o] * ch2A[o];
                    if (o > 0)  acc += w[o - 1] * cliA[o - 1];
                    if (o < 18) acc += w[o + 1] * cliA[o + 1];
                    nw[o] = acc;
                }
                #pragma unroll
                for (int o = 0; o < 19; o++) w[o] = nw[o];
                #pragma unroll
                for (int o2 = 0; o2 < 13; o2++) {
                    Pt[o2] += pcF[k] * w[o2 + 3];
                    Qt[o2] += qcF[k] * w[o2 + 3];
                }
            }
            #pragma unroll
            for (int j = 0; j < 13; j++)
                gOp[0][58 + j][p] = make_float2(Pt[j], Qt[j]);
        }
    }
    if (is_chain) {
        const float K0 = 0.209439510239f;
        const float SINE = 0.0261769483f;
        float ww  = sqrtf(2.0f * logf(2.0f)) / (K0 * SINE);
        float amp = 1.0f / (sqrtf(3.14159265358979f) * ww);
        for (int p = tid; p < NPTS; p += NTH) {
            float z = (2000.0f / 499.0f) * (float)p;
            float a = (z - 100.0f) / ww;
            v0[p] = make_float2(amp * expf(-a * a), 0.f);
        }
    }
    gsync(myg);

    // ============ Ladder + overlapped chain-start products ============
    float2* src = v0;
    float2* dst = v1;
    for (int L = 0; L < NLVL - 1; L++) {
        const int Rin  = cRLV[L];
        const int Rout = cRLV[L + 1];
        const int Win   = 2 * Rin + 1;
        const int rowsIn = 4 + 2 * Rin;
        const int rowsP  = rowsIn + 1;
        const int r0 = 4 * b;

        for (int i = tid; i < Win * rowsIn; i += NTH) {
            int tap = i / rowsIn;
            int lr  = i - tap * rowsIn;
            int r   = r0 - Rin + lr;
            sbuf[tap * rowsP + lr] =
                (r >= 0 && r < NPTS) ? gOp[L][64 - Rin + tap][r] : make_float2(0.f, 0.f);
        }
        __syncthreads();

        const int Wout = 2 * Rout + 1;
        for (int i = tid; i < 4 * Wout; i += NTH) {
            int row = i / Wout;
            int d   = i - row * Wout - Rout;
            int r   = r0 + row;
            if (r >= NPTS) continue;
            int olo = (-Rin > d - Rin) ? -Rin : d - Rin;
            int ohi = ( Rin < d + Rin) ?  Rin : d + Rin;
            float pp = 0.f, qq = 0.f;
            for (int o = olo; o <= ohi; o++) {
                float2 A = sbuf[(o + Rin) * rowsP + (Rin + row)];
                float2 B = sbuf[(d - o + Rin) * rowsP + (Rin + row + o)];
                pp += A.x * B.x - A.y * B.y;
                qq += A.x * B.y + A.y * B.x;
            }
            gOp[L + 1][64 + d][r] = make_float2(pp, qq);
        }
        gsync(myg);

        if (is_chain && ((n0 >> (L + 1)) & 1)) {
            const int R = cRLV[L + 1];
            for (int p = tid; p < NPTS; p += NTH) {
                int olo = (p < R) ? -p : -R;
                int ohi = (NPTS - 1 - p < R) ? NPTS - 1 - p : R;
                float a1x = 0.f, a1y = 0.f, a2x = 0.f, a2y = 0.f;
                for (int o = olo; o <= ohi; o++) {
                    float2 PQ = gOp[L + 1][64 + o][p];
                    float2 v  = src[p + o];
                    a1x += PQ.x * v.x;  a1y += PQ.x * v.y;
                    a2x += PQ.y * v.x;  a2y += PQ.y * v.y;
                }
                dst[p] = make_float2(a1x - a2y, a1y + a2x);
            }
            __syncthreads();
            float2* tmp = src; src = dst; dst = tmp;
        }
    }

    // ================= P9: chains, fully local =================
    if (is_chain) {
        u64* YA = (u64*)sbuf;
        u64* YB = YA + YSLOTS;
        const int p0 = 2 * tid;
        const int half = n_save * NPTS;

        u64 Pa[13], Qa[13], Pb[13], Qb[13];
        #pragma unroll
        for (int j = 0; j < 13; j++) {
            float2 t0 = (p0 < NPTS) ? gOp[0][58 + j][p0] : make_float2(0.f, 0.f);
            float2 t1 = (p0 + 1 < NPTS) ? gOp[0][58 + j][p0 + 1] : make_float2(0.f, 0.f);
            Pa[j] = pk2(t0.x, t0.x);  Qa[j] = pk2(t0.y, t0.y);
            Pb[j] = pk2(t1.x, t1.x);  Qb[j] = pk2(t1.y, t1.y);
        }

        u64 y0p = 0ull, y1p = 0ull;
        if (p0 < NPTS) {
            F2U a; a.f = src[p0]; y0p = a.u;
            if (p0 + 1 < NPTS) { a.f = src[p0 + 1]; y1p = a.u; }
        }
        __syncthreads();
        for (int j = tid; j < YSLOTS; j += NTH) { YA[j] = 0ull; YB[j] = 0ull; }
        __syncthreads();
        YA[p0 + 6] = y0p;
        YA[p0 + 7] = y1p;
        __syncthreads();

        if (p0 < NPTS) {
            int row = n0 * NPTS + p0;
            out[row]        = lo2(y0p);
            out[half + row] = hi2(y0p);
            if (p0 + 1 < NPTS) {
                out[row + 1]        = lo2(y1p);
                out[half + row + 1] = hi2(y1p);
            }
        }

        const float4* RA = ((const float4*)YA) + tid;
        const float4* RB = ((const float4*)YB) + tid;
        float4* WA = ((float4*)YA) + (tid + 3);
        float4* WB = ((float4*)YB) + (tid + 3);

#define STEP(RSRC, WDST)                                                     \
    {                                                                        \
        u64 v[14];                                                           \
        _Pragma("unroll")                                                    \
        for (int j = 0; j < 7; j++) {                                        \
            float4 f = (RSRC)[j];                                            \
            v[2*j] = pk2(f.x, f.y); v[2*j + 1] = pk2(f.z, f.w);              \
        }                                                                    \
        u64 pa0 = mul2(Pa[0], v[0]);   u64 pa1 = mul2(Pa[1], v[1]);          \
        pa0 = fma2(Pa[2],  v[2],  pa0); pa1 = fma2(Pa[3],  v[3],  pa1);      \
        pa0 = fma2(Pa[4],  v[4],  pa0); pa1 = fma2(Pa[5],  v[5],  pa1);      \
        pa0 = fma2(Pa[6],  v[6],  pa0); pa1 = fma2(Pa[7],  v[7],  pa1);      \
        pa0 = fma2(Pa[8],  v[8],  pa0); pa1 = fma2(Pa[9],  v[9],  pa1);      \
        pa0 = fma2(Pa[10], v[10], pa0); pa1 = fma2(Pa[11], v[11], pa1);      \
        pa0 = fma2(Pa[12], v[12], pa0);                                      \
        u64 qa0 = mul2(Qa[0], v[0]);   u64 qa1 = mul2(Qa[1], v[1]);          \
        qa0 = fma2(Qa[2],  v[2],  qa0); qa1 = fma2(Qa[3],  v[3],  qa1);      \
        qa0 = fma2(Qa[4],  v[4],  qa0); qa1 = fma2(Qa[5],  v[5],  qa1);      \
        qa0 = fma2(Qa[6],  v[6],  qa0); qa1 = fma2(Qa[7],  v[7],  qa1);      \
        qa0 = fma2(Qa[8],  v[8],  qa0); qa1 = fma2(Qa[9],  v[9],  qa1);      \
        qa0 = fma2(Qa[10], v[10], qa0); qa1 = fma2(Qa[11], v[11], qa1);      \
        qa0 = fma2(Qa[12], v[12], qa0);                                      \
        u64 pb0 = mul2(Pb[0], v[1]);   u64 pb1 = mul2(Pb[1], v[2]);          \
        pb0 = fma2(Pb[2],  v[3],  pb0); pb1 = fma2(Pb[3],  v[4],  pb1);      \
        pb0 = fma2(Pb[4],  v[5],  pb0); pb1 = fma2(Pb[5],  v[6],  pb1);      \
        pb0 = fma2(Pb[6],  v[7],  pb0); pb1 = fma2(Pb[7],  v[8],  pb1);      \
        pb0 = fma2(Pb[8],  v[9],  pb0); pb1 = fma2(Pb[9],  v[10], pb1);      \
        pb0 = fma2(Pb[10], v[11], pb0); pb1 = fma2(Pb[11], v[12], pb1);      \
        pb0 = fma2(Pb[12], v[13], pb0);                                      \
        u64 qb0 = mul2(Qb[0], v[1]);   u64 qb1 = mul2(Qb[1], v[2]);          \
        qb0 = fma2(Qb[2],  v[3],  qb0); qb1 = fma2(Qb[3],  v[4],  qb1);      \
        qb0 = fma2(Qb[4],  v[5],  qb0); qb1 = fma2(Qb[5],  v[6],  qb1);      \
        qb0 = fma2(Qb[6],  v[7],  qb0); qb1 = fma2(Qb[7],  v[8],  qb1);      \
        qb0 = fma2(Qb[8],  v[9],  qb0); qb1 = fma2(Qb[9],  v[10], qb1);      \
        qb0 = fma2(Qb[10], v[11], qb0); qb1 = fma2(Qb[11], v[12], qb1);      \
        qb0 = fma2(Qb[12], v[13], qb0);                                      \
        u64 uP0 = add2(pa0, pa1);  u64 uQ0 = add2(qa0, qa1);                 \
        u64 uP1 = add2(pb0, pb1);  u64 uQ1 = add2(qb0, qb1);                 \
        F2U U0, V0, U1, V1; U0.u = uP0; V0.u = uQ0; U1.u = uP1; V1.u = uQ1;  \
        y0p = pk2(U0.f.x - V0.f.y, U0.f.y + V0.f.x);                         \
        y1p = pk2(U1.f.x - V1.f.y, U1.f.y + V1.f.x);                         \
        float4 sv; sv.x = lo2(y0p); sv.y = hi2(y0p);                         \
        sv.z = lo2(y1p); sv.w = hi2(y1p);                                    \
        *(WDST) = sv;                                                        \
        __syncthreads();                                                     \
    }

        int lastrow = (n0 + MITV < nitv) ? n0 + MITV : nitv;
        bool next_exists = (b + 1 < NCH) && (MITV * (b + 1) <= nitv);
        int top = next_exists ? (MITV * (b + 1) - 1) : lastrow;
        int napps = top - n0;

        int fl = 0;
        for (int a = 0; a < napps; a++) {
            if (!fl) { STEP(RA, WB) } else { STEP(RB, WA) }
            if (p0 < NPTS) {
                int row = (n0 + 1 + a) * NPTS + p0;
                out[row]        = lo2(y0p);
                out[half + row] = hi2(y0p);
                if (p0 + 1 < NPTS) {
                    out[row + 1]        = lo2(y1p);
                    out[half + row + 1] = hi2(y1p);
                }
            }
            fl ^= 1;
        }
#undef STEP
    }
}

extern "C" void kernel_launch(void* const* d_in, const int* in_sizes, int n_in,
                              void* d_out, int out_size)
{
    int p_idx = 1, t_idx = 0;
    if (n_in >= 2 && in_sizes[0] == 2 && in_sizes[1] != 2) { p_idx = 0; t_idx = 1; }
    const float* params = (const float*)d_in[p_idx];
    const int n_save = in_sizes[t_idx];

    cudaFuncSetAttribute(pe_all, cudaFuncAttributeMaxDynamicSharedMemorySize, SMEM_BYTES);
    pe_all<<<NBLK, NTH, SMEM_BYTES>>>(params, (float*)d_out, n_save);
}